// round 10
// baseline (speedup 1.0000x reference)
#include <cuda_runtime.h>
#include <cuda_bf16.h>
#include <math.h>
#include <stdint.h>

#define BB 2
#define SS 2048
#define HH 12
#define DD 768
#define FF (4*DD)

typedef __nv_bfloat16 bf16;

constexpr long QKV_E = (long)BB*HH*SS*DD;
constexpr long P_E   = (long)BB*HH*SS*SS;
constexpr long CTX_E = (long)BB*SS*HH*DD;
constexpr long OUT_E = (long)BB*SS*DD;
constexpr long FFH_E = (long)BB*SS*FF;
constexpr long WQ_E  = (long)HH*DD*DD;
constexpr long WO_E  = (long)DD*HH*DD;
constexpr long W1_E  = (long)FF*DD;

// ---- scratch (__device__ globals; no allocation allowed) ----
__device__ bf16 g_xh[OUT_E], g_xl[OUT_E];
__device__ bf16 g_WqTh[WQ_E], g_WqTl[WQ_E];
__device__ bf16 g_WkTh[WQ_E], g_WkTl[WQ_E];
__device__ bf16 g_WvTh[WQ_E], g_WvTl[WQ_E];
__device__ bf16 g_Woh[WO_E], g_Wol[WO_E];
__device__ bf16 g_W1h[W1_E], g_W1l[W1_E];
__device__ bf16 g_W2h[W1_E], g_W2l[W1_E];
__device__ bf16 g_Qh[QKV_E], g_Ql[QKV_E];
__device__ bf16 g_Kh[QKV_E], g_Kl[QKV_E];
__device__ float g_V[QKV_E];
__device__ bf16 g_VTh[QKV_E], g_VTl[QKV_E];
__device__ float g_P[P_E];
__device__ bf16 g_Ph[P_E], g_Pl[P_E];
__device__ bf16 g_ch[CTX_E], g_cl[CTX_E];
__device__ float g_attn[OUT_E];
__device__ bf16 g_xnh[OUT_E], g_xnl[OUT_E];
__device__ bf16 g_fh[FFH_E], g_fl[FFH_E];

// ---------------------------------------------------------------------------
__device__ __forceinline__ uint32_t s2u(const void* p){
    uint32_t a;
    asm("{ .reg .u64 t; cvta.to.shared.u64 t, %1; cvt.u32.u64 %0, t; }"
        : "=r"(a) : "l"(p));
    return a;
}
__device__ __forceinline__ void split2(float v, bf16& h, bf16& l){
    h = __float2bfloat16(v);
    l = __float2bfloat16(v - __bfloat162float(h));
}

#define CP_COMMIT() asm volatile("cp.async.commit_group;" ::: "memory")
#define CP_WAIT1()  asm volatile("cp.async.wait_group 1;" ::: "memory")
#define CP_WAIT0()  asm volatile("cp.async.wait_group 0;" ::: "memory")

__device__ __forceinline__ void ldm_x4(uint32_t* r, uint32_t a){
    asm volatile("ldmatrix.sync.aligned.m8n8.x4.shared.b16 {%0,%1,%2,%3}, [%4];"
        : "=r"(r[0]), "=r"(r[1]), "=r"(r[2]), "=r"(r[3]) : "r"(a));
}

#define MMA(d, a, b) \
    asm volatile("mma.sync.aligned.m16n8k16.row.col.f32.bf16.bf16.f32 " \
        "{%0,%1,%2,%3}, {%4,%5,%6,%7}, {%8,%9}, {%0,%1,%2,%3};" \
        : "+f"((d)[0]), "+f"((d)[1]), "+f"((d)[2]), "+f"((d)[3]) \
        : "r"((a)[0]), "r"((a)[1]), "r"((a)[2]), "r"((a)[3]), \
          "r"((b)[0]), "r"((b)[1]))

// SMEM stage layout: Ah @0, Al @10240, Bh @20480, Bl @30720; rows padded to 80B.
#define STAGE_B 40960
#define NSTAGE  2

__device__ __forceinline__ void stage_load(
    char* sbase, const bf16* __restrict__ Ah, const bf16* __restrict__ Al,
    const bf16* __restrict__ Bh, const bf16* __restrict__ Bl,
    int m0, int n0, int k0, int lda, int ldb, int tid)
{
#pragma unroll
    for (int t = 0; t < 8; ++t){
        const int q = tid + t * 256;
        const int tile = q >> 9;
        const int rem  = q & 511;
        const int r    = rem >> 2;
        const int c    = rem & 3;
        const bf16* gp;
        if (tile == 0)      gp = Ah + (long)(m0 + r) * lda + k0 + c * 8;
        else if (tile == 1) gp = Al + (long)(m0 + r) * lda + k0 + c * 8;
        else if (tile == 2) gp = Bh + (long)(n0 + r) * ldb + k0 + c * 8;
        else                gp = Bl + (long)(n0 + r) * ldb + k0 + c * 8;
        const uint32_t so = s2u(sbase + tile * 10240 + r * 80 + c * 16);
        asm volatile("cp.async.cg.shared.global [%0], [%1], 16;" :: "r"(so), "l"(gp));
    }
}

__device__ __forceinline__ void stage_mma(uint32_t su, int wm, int wn, int lane,
                                          float (*acc)[4][4])
{
    const int lr = lane & 7, g = lane >> 3;
    const uint32_t aoff = (uint32_t)((((g & 1) * 8 + lr) * 80) + (g >> 1) * 16);
    const uint32_t boff = (uint32_t)((((g >> 1) * 8 + lr) * 80) + (g & 1) * 16);
    const uint32_t uAh = su + (uint32_t)(wm * 80) + aoff;
    const uint32_t uAl = uAh + 10240;
    const uint32_t uBh = su + 20480 + (uint32_t)(wn * 80) + boff;
    const uint32_t uBl = uBh + 10240;

#pragma unroll
    for (int kk = 0; kk < 2; ++kk){
        uint32_t ah[4][4], al[4][4], bh[2][4], bl[2][4];
#pragma unroll
        for (int mi = 0; mi < 4; ++mi) ldm_x4(ah[mi], uAh + mi * 1280 + kk * 32);
#pragma unroll
        for (int j = 0; j < 2; ++j)    ldm_x4(bh[j], uBh + j * 1280 + kk * 32);
#pragma unroll
        for (int mi = 0; mi < 4; ++mi)
#pragma unroll
            for (int ni = 0; ni < 4; ++ni)
                MMA(acc[mi][ni], ah[mi], &bh[ni >> 1][(ni & 1) * 2]);
#pragma unroll
        for (int j = 0; j < 2; ++j)    ldm_x4(bl[j], uBl + j * 1280 + kk * 32);
#pragma unroll
        for (int mi = 0; mi < 4; ++mi)
#pragma unroll
            for (int ni = 0; ni < 4; ++ni)
                MMA(acc[mi][ni], ah[mi], &bl[ni >> 1][(ni & 1) * 2]);
#pragma unroll
        for (int mi = 0; mi < 4; ++mi) ldm_x4(al[mi], uAl + mi * 1280 + kk * 32);
#pragma unroll
        for (int mi = 0; mi < 4; ++mi)
#pragma unroll
            for (int ni = 0; ni < 4; ++ni)
                MMA(acc[mi][ni], al[mi], &bh[ni >> 1][(ni & 1) * 2]);
    }
}

// ---------------------------------------------------------------------------
// HMMA GEMM: C[M,N] = A[M,K] * B[N,K]^T (both K-major bf16 hi/lo), fp32 acc.
// 2-stage cp.async double buffer, 2 CTAs/SM. Correct visibility protocol:
// wait_group -> __syncthreads() -> consume (cross-thread cp.async data is only
// visible after a barrier that follows every producer's wait).
// EPI: 0=f32 store, 1=f32*scale, 2=GELU->hi/lo, 3=+Res->f32, 4=hi/lo split
// ---------------------------------------------------------------------------
template<int EPI, bool CAUSAL, bool KLIM>
__global__ __launch_bounds__(256, 2) void mm_gemm(
    const bf16* __restrict__ Ah, const bf16* __restrict__ Al,
    const bf16* __restrict__ Bh, const bf16* __restrict__ Bl,
    float* __restrict__ C, bf16* __restrict__ Ch, bf16* __restrict__ Cl,
    const float* __restrict__ Res,
    int K, int lda, int ldb, int ldc,
    long sAb, long sAh_, long sBb, long sBh_, long sCb, long sCh_,
    int Hn, float scale)
{
    const int m0 = blockIdx.y * 128;
    const int n0 = blockIdx.x * 128;
    if (CAUSAL && n0 > m0) return;

    const int z = blockIdx.z, b_ = z / Hn, h_ = z - b_ * Hn;
    Ah += b_*sAb + h_*sAh_;  Al += b_*sAb + h_*sAh_;
    Bh += b_*sBb + h_*sBh_;  Bl += b_*sBb + h_*sBh_;
    const long cOff = b_*sCb + h_*sCh_;

    extern __shared__ char sm[];
    const int tid = threadIdx.x, lane = tid & 31, wid = tid >> 5;
    const int wm = (wid >> 2) * 64, wn = (wid & 3) * 32;

    const int Keff = KLIM ? min(K, m0 + 128) : K;
    const int nst  = Keff >> 5;

    float acc[4][4][4];
#pragma unroll
    for (int i = 0; i < 4; ++i)
#pragma unroll
        for (int j = 0; j < 4; ++j)
#pragma unroll
            for (int r = 0; r < 4; ++r) acc[i][j][r] = 0.f;

    stage_load(sm, Ah, Al, Bh, Bl, m0, n0, 0, lda, ldb, tid);
    CP_COMMIT();

    for (int ks = 0; ks < nst; ++ks){
        if (ks + 1 < nst){
            stage_load(sm + ((ks + 1) & 1) * STAGE_B, Ah, Al, Bh, Bl,
                       m0, n0, (ks + 1) * 32, lda, ldb, tid);
            CP_COMMIT();
            CP_WAIT1();       // stage ks's group complete (own copies)
        } else {
            CP_WAIT0();
        }
        __syncthreads();      // publish ALL threads' stage-ks data
        stage_mma(s2u(sm) + (uint32_t)((ks & 1) * STAGE_B), wm, wn, lane, acc);
        __syncthreads();      // all consumed buffer ks&1 before next overwrite
    }

    // Epilogue: direct global stores (2 fp32 per thread per fragment row)
    const int rbase = m0 + wm + (lane >> 2);
    const int cbase = n0 + wn + (lane & 3) * 2;
#pragma unroll
    for (int mi = 0; mi < 4; ++mi){
#pragma unroll
        for (int ni = 0; ni < 4; ++ni){
#pragma unroll
            for (int half = 0; half < 2; ++half){
                const long r = rbase + mi * 16 + half * 8;
                const long n = cbase + ni * 8;
                const long o = cOff + r * (long)ldc + n;
                float v0 = acc[mi][ni][half * 2];
                float v1 = acc[mi][ni][half * 2 + 1];
                if (EPI == 0){
                    float2 s; s.x = v0; s.y = v1;
                    *reinterpret_cast<float2*>(C + o) = s;
                } else if (EPI == 1){
                    float2 s; s.x = v0 * scale; s.y = v1 * scale;
                    *reinterpret_cast<float2*>(C + o) = s;
                } else if (EPI == 2){
                    const float g0 = 0.5f * v0 * (1.f + erff(v0 * 0.70710678118654752f));
                    const float g1 = 0.5f * v1 * (1.f + erff(v1 * 0.70710678118654752f));
                    bf16 h0, l0, h1, l1;
                    split2(g0, h0, l0); split2(g1, h1, l1);
                    __nv_bfloat162 hh; hh.x = h0; hh.y = h1;
                    __nv_bfloat162 ll; ll.x = l0; ll.y = l1;
                    *reinterpret_cast<__nv_bfloat162*>(Ch + o) = hh;
                    *reinterpret_cast<__nv_bfloat162*>(Cl + o) = ll;
                } else if (EPI == 3){
                    const float2 rv = *reinterpret_cast<const float2*>(Res + o);
                    float2 s; s.x = v0 + rv.x; s.y = v1 + rv.y;
                    *reinterpret_cast<float2*>(C + o) = s;
                } else {
                    bf16 h0, l0, h1, l1;
                    split2(v0, h0, l0); split2(v1, h1, l1);
                    __nv_bfloat162 hh; hh.x = h0; hh.y = h1;
                    __nv_bfloat162 ll; ll.x = l0; ll.y = l1;
                    *reinterpret_cast<__nv_bfloat162*>(Ch + o) = hh;
                    *reinterpret_cast<__nv_bfloat162*>(Cl + o) = ll;
                }
            }
        }
    }
}

// ---------------------------------------------------------------------------
// fused fp32 -> bf16 hi/lo split over 4 arrays (one launch)
// ---------------------------------------------------------------------------
__global__ __launch_bounds__(256) void split4_k(
    const float* __restrict__ X0, bf16* __restrict__ h0, bf16* __restrict__ l0, long n0,
    const float* __restrict__ X1, bf16* __restrict__ h1, bf16* __restrict__ l1, long n1,
    const float* __restrict__ X2, bf16* __restrict__ h2, bf16* __restrict__ l2, long n2,
    const float* __restrict__ X3, bf16* __restrict__ h3, bf16* __restrict__ l3, long n3)
{
    const long tot = n0 + n1 + n2 + n3;
    long i  = blockIdx.x * 256L + threadIdx.x;
    long st = (long)gridDim.x * 256L;
    for (; i < tot; i += st){
        const float* X; bf16 *hp, *lp; long j = i;
        if (j < n0){ X = X0; hp = h0; lp = l0; }
        else if ((j -= n0) < n1){ X = X1; hp = h1; lp = l1; }
        else if ((j -= n1) < n2){ X = X2; hp = h2; lp = l2; }
        else { j -= n2; X = X3; hp = h3; lp = l3; }
        bf16 h, l; split2(X[j], h, l);
        hp[j] = h; lp[j] = l;
    }
}

// transpose + split: per z, X[R,C] row-major -> out[C,R] hi/lo
__global__ __launch_bounds__(256) void split_t_k(const float* __restrict__ X,
                                                 bf16* __restrict__ hi,
                                                 bf16* __restrict__ lo,
                                                 int R, int C, long sX, long sO)
{
    __shared__ float t[32][33];
    const float* Xz = X + (long)blockIdx.z * sX;
    const int c0 = blockIdx.x * 32, r0 = blockIdx.y * 32;
    const int tx = threadIdx.x & 31, ty = threadIdx.x >> 5;
#pragma unroll
    for (int i = 0; i < 32; i += 8)
        t[ty + i][tx] = Xz[(long)(r0 + ty + i) * C + c0 + tx];
    __syncthreads();
#pragma unroll
    for (int i = 0; i < 32; i += 8){
        const float v = t[tx][ty + i];
        const long o = (long)blockIdx.z * sO + (long)(c0 + ty + i) * R + r0 + tx;
        bf16 h, l; split2(v, h, l);
        hi[o] = h; lo[o] = l;
    }
}

// ---------------------------------------------------------------------------
// Causal softmax: fp32 scores row -> bf16 hi/lo probs (zero-padded to 128)
// ---------------------------------------------------------------------------
__global__ __launch_bounds__(256) void softmax_k(const float* __restrict__ P,
                                                 bf16* __restrict__ Ph,
                                                 bf16* __restrict__ Pl)
{
    const long r  = blockIdx.x;
    const int  q  = (int)(r % SS);
    const float* row = P + r * (long)SS;
    const int len = q + 1;
    const int t   = threadIdx.x;

    float v[8];
    float mx = -INFINITY;
#pragma unroll
    for (int i = 0; i < 8; ++i){
        const int k = t + i * 256;
        v[i] = (k < len) ? row[k] : -INFINITY;
        mx = fmaxf(mx, v[i]);
    }
    __shared__ float red[256];
    red[t] = mx; __syncthreads();
    for (int s = 128; s > 0; s >>= 1){
        if (t < s) red[t] = fmaxf(red[t], red[t + s]);
        __syncthreads();
    }
    mx = red[0]; __syncthreads();

    float sum = 0.f;
#pragma unroll
    for (int i = 0; i < 8; ++i){
        const int k = t + i * 256;
        if (k < len){ v[i] = expf(v[i] - mx); sum += v[i]; }
        else v[i] = 0.f;
    }
    red[t] = sum; __syncthreads();
    for (int s = 128; s > 0; s >>= 1){
        if (t < s) red[t] += red[t + s];
        __syncthreads();
    }
    const float inv = 1.f / red[0];

    const int zlen = (q / 128 + 1) * 128;
    bf16* ph = Ph + r * (long)SS;
    bf16* pl = Pl + r * (long)SS;
#pragma unroll
    for (int i = 0; i < 8; ++i){
        const int k = t + i * 256;
        if (k < zlen){
            bf16 h, l; split2(v[i] * inv, h, l);
            ph[k] = h; pl[k] = l;
        }
    }
}

// LayerNorm (no affine) -> bf16 hi/lo
__global__ __launch_bounds__(256) void ln_k(const float* __restrict__ X,
                                            bf16* __restrict__ Yh,
                                            bf16* __restrict__ Yl)
{
    const long r = blockIdx.x;
    const float* x = X + r * (long)DD;
    const int t = threadIdx.x;

    float s = 0.f, s2 = 0.f;
#pragma unroll
    for (int i = 0; i < 3; ++i){
        const float v = x[t + i * 256];
        s += v; s2 += v * v;
    }
    __shared__ float rs[256], rs2[256];
    rs[t] = s; rs2[t] = s2; __syncthreads();
    for (int st = 128; st > 0; st >>= 1){
        if (t < st){ rs[t] += rs[t + st]; rs2[t] += rs2[t + st]; }
        __syncthreads();
    }
    const float mu   = rs[0] * (1.f / DD);
    const float var  = rs2[0] * (1.f / DD) - mu * mu;
    const float rstd = rsqrtf(var + 1e-5f);
#pragma unroll
    for (int i = 0; i < 3; ++i){
        const int k = t + i * 256;
        bf16 h, l; split2((x[k] - mu) * rstd, h, l);
        Yh[r * (long)DD + k] = h; Yl[r * (long)DD + k] = l;
    }
}

// ---------------------------------------------------------------------------
extern "C" void kernel_launch(void* const* d_in, const int* in_sizes, int n_in,
                              void* d_out, int out_size)
{
    const float* x  = (const float*)d_in[0];
    const float* Wq = (const float*)d_in[1];
    const float* Wk = (const float*)d_in[2];
    const float* Wv = (const float*)d_in[3];
    const float* Wo = (const float*)d_in[4];
    const float* W1 = (const float*)d_in[5];
    const float* W2 = (const float*)d_in[6];
    float* out = (float*)d_out;

    bf16 *xh,*xl,*WqTh,*WqTl,*WkTh,*WkTl,*WvTh,*WvTl,*Woh,*Wol,*W1h,*W1l,*W2h,*W2l;
    bf16 *Qh,*Ql,*Kh,*Kl,*VTh,*VTl,*Ph,*Pl,*ch,*cl,*xnh,*xnl,*fh,*fl;
    float *V,*P,*attn;
    cudaGetSymbolAddress((void**)&xh, g_xh);   cudaGetSymbolAddress((void**)&xl, g_xl);
    cudaGetSymbolAddress((void**)&WqTh, g_WqTh); cudaGetSymbolAddress((void**)&WqTl, g_WqTl);
    cudaGetSymbolAddress((void**)&WkTh, g_WkTh); cudaGetSymbolAddress((void**)&WkTl, g_WkTl);
    cudaGetSymbolAddress((void**)&WvTh, g_WvTh); cudaGetSymbolAddress((void**)&WvTl, g_WvTl);
    cudaGetSymbolAddress((void**)&Woh, g_Woh); cudaGetSymbolAddress((void**)&Wol, g_Wol);
    cudaGetSymbolAddress((void**)&W1h, g_W1h); cudaGetSymbolAddress((void**)&W1l, g_W1l);
    cudaGetSymbolAddress((void**)&W2h, g_W2h); cudaGetSymbolAddress((void**)&W2l, g_W2l);
    cudaGetSymbolAddress((void**)&Qh, g_Qh);   cudaGetSymbolAddress((void**)&Ql, g_Ql);
    cudaGetSymbolAddress((void**)&Kh, g_Kh);   cudaGetSymbolAddress((void**)&Kl, g_Kl);
    cudaGetSymbolAddress((void**)&V, g_V);
    cudaGetSymbolAddress((void**)&VTh, g_VTh); cudaGetSymbolAddress((void**)&VTl, g_VTl);
    cudaGetSymbolAddress((void**)&P, g_P);
    cudaGetSymbolAddress((void**)&Ph, g_Ph);   cudaGetSymbolAddress((void**)&Pl, g_Pl);
    cudaGetSymbolAddress((void**)&ch, g_ch);   cudaGetSymbolAddress((void**)&cl, g_cl);
    cudaGetSymbolAddress((void**)&attn, g_attn);
    cudaGetSymbolAddress((void**)&xnh, g_xnh); cudaGetSymbolAddress((void**)&xnl, g_xnl);
    cudaGetSymbolAddress((void**)&fh, g_fh);   cudaGetSymbolAddress((void**)&fl, g_fl);

    const int SMEMB = NSTAGE * STAGE_B;   // 81920 -> 2 CTAs/SM
    cudaFuncSetAttribute(mm_gemm<4,false,false>, cudaFuncAttributeMaxDynamicSharedMemorySize, SMEMB);
    cudaFuncSetAttribute(mm_gemm<0,false,false>, cudaFuncAttributeMaxDynamicSharedMemorySize, SMEMB);
    cudaFuncSetAttribute(mm_gemm<1,true ,false>, cudaFuncAttributeMaxDynamicSharedMemorySize, SMEMB);
    cudaFuncSetAttribute(mm_gemm<4,false,true >, cudaFuncAttributeMaxDynamicSharedMemorySize, SMEMB);
    cudaFuncSetAttribute(mm_gemm<2,false,false>, cudaFuncAttributeMaxDynamicSharedMemorySize, SMEMB);
    cudaFuncSetAttribute(mm_gemm<3,false,false>, cudaFuncAttributeMaxDynamicSharedMemorySize, SMEMB);

    const long sSD  = (long)SS*DD;
    const long sBSD = (long)HH*SS*DD;

    // --- prep: fused flat splits + transposed weight splits ---
    split4_k<<<8192, 256>>>(x, xh, xl, OUT_E,
                            Wo, Woh, Wol, WO_E,
                            W1, W1h, W1l, W1_E,
                            W2, W2h, W2l, W1_E);
    {
        dim3 g(DD/32, DD/32, HH);
        split_t_k<<<g, 256>>>(Wq, WqTh, WqTl, DD, DD, (long)DD*DD, (long)DD*DD);
        split_t_k<<<g, 256>>>(Wk, WkTh, WkTl, DD, DD, (long)DD*DD, (long)DD*DD);
        split_t_k<<<g, 256>>>(Wv, WvTh, WvTl, DD, DD, (long)DD*DD, (long)DD*DD);
    }

    // --- Q, K projections (split output), V projection (fp32) ---
    {
        dim3 g(DD/128, SS/128, BB*HH);
        mm_gemm<4,false,false><<<g, 256, SMEMB>>>(
            xh, xl, WqTh, WqTl, nullptr, Qh, Ql, nullptr,
            DD, DD, DD, DD, sSD, 0L, 0L, (long)DD*DD, sBSD, sSD, HH, 1.f);
        mm_gemm<4,false,false><<<g, 256, SMEMB>>>(
            xh, xl, WkTh, WkTl, nullptr, Kh, Kl, nullptr,
            DD, DD, DD, DD, sSD, 0L, 0L, (long)DD*DD, sBSD, sSD, HH, 1.f);
        mm_gemm<0,false,false><<<g, 256, SMEMB>>>(
            xh, xl, WvTh, WvTl, V, nullptr, nullptr, nullptr,
            DD, DD, DD, DD, sSD, 0L, 0L, (long)DD*DD, sBSD, sSD, HH, 1.f);
    }
    // V -> V^T hi/lo (per b,h: [2048,768] -> [768,2048])
    {
        dim3 g(DD/32, SS/32, BB*HH);
        split_t_k<<<g, 256>>>(V, VTh, VTl, SS, DD, sSD, sSD);
    }
    // --- scores = (Q K^T)/sqrt(D), causal tile skip, fp32 out ---
    {
        dim3 g(SS/128, SS/128, BB*HH);
        mm_gemm<1,true,false><<<g, 256, SMEMB>>>(
            Qh, Ql, Kh, Kl, P, nullptr, nullptr, nullptr,
            DD, DD, DD, SS, sBSD, sSD, sBSD, sSD,
            (long)HH*SS*SS, (long)SS*SS, HH, rsqrtf((float)DD));
    }
    // --- softmax -> hi/lo ---
    softmax_k<<<BB*HH*SS, 256>>>(P, Ph, Pl);
    // --- ctx = P V (K-limited), split output scattered to [B,S,H*D] ---
    {
        dim3 g(DD/128, SS/128, BB*HH);
        mm_gemm<4,false,true><<<g, 256, SMEMB>>>(
            Ph, Pl, VTh, VTl, nullptr, ch, cl, nullptr,
            SS, SS, SS, HH*DD,
            (long)HH*SS*SS, (long)SS*SS, (long)HH*DD*SS, (long)DD*SS,
            (long)SS*HH*DD, (long)DD, HH, 1.f);
    }
    // --- attn = ctx @ Wo^T (fp32) ---
    {
        dim3 g(DD/128, (BB*SS)/128, 1);
        mm_gemm<0,false,false><<<g, 256, SMEMB>>>(
            ch, cl, Woh, Wol, attn, nullptr, nullptr, nullptr,
            HH*DD, HH*DD, HH*DD, DD, 0L,0L,0L,0L,0L,0L, 1, 1.f);
    }
    // --- LN -> hi/lo ---
    ln_k<<<BB*SS, 256>>>(attn, xnh, xnl);
    // --- FFN1: GELU(xn @ W1^T) -> hi/lo ---
    {
        dim3 g(FF/128, (BB*SS)/128, 1);
        mm_gemm<2,false,false><<<g, 256, SMEMB>>>(
            xnh, xnl, W1h, W1l, nullptr, fh, fl, nullptr,
            DD, DD, DD, FF, 0L,0L,0L,0L,0L,0L, 1, 1.f);
    }
    // --- FFN2: out = attn + ffh @ W2^T ---
    {
        dim3 g(DD/128, (BB*SS)/128, 1);
        mm_gemm<3,false,false><<<g, 256, SMEMB>>>(
            fh, fl, W2h, W2l, out, nullptr, nullptr, attn,
            FF, FF, FF, DD, 0L,0L,0L,0L,0L,0L, 1, 1.f);
    }
}

// round 13
// speedup vs baseline: 1.3503x; 1.3503x over previous
#include <cuda_runtime.h>
#include <cuda_bf16.h>
#include <math.h>
#include <stdint.h>

#define BB 2
#define SS 2048
#define HH 12
#define DD 768
#define FF (4*DD)

typedef __nv_bfloat16 bf16;

constexpr long QKV_E = (long)BB*HH*SS*DD;
constexpr long P_E   = (long)BB*HH*SS*SS;
constexpr long CTX_E = (long)BB*SS*HH*DD;
constexpr long OUT_E = (long)BB*SS*DD;
constexpr long FFH_E = (long)BB*SS*FF;
constexpr long WQ_E  = (long)HH*DD*DD;
constexpr long WO_E  = (long)DD*HH*DD;
constexpr long W1_E  = (long)FF*DD;

// ---- scratch (__device__ globals; no allocation allowed) ----
__device__ bf16 g_xh[OUT_E], g_xl[OUT_E];
__device__ bf16 g_WqTh[WQ_E], g_WqTl[WQ_E];
__device__ bf16 g_WkTh[WQ_E], g_WkTl[WQ_E];
__device__ bf16 g_WvTh[WQ_E], g_WvTl[WQ_E];
__device__ bf16 g_Woh[WO_E], g_Wol[WO_E];
__device__ bf16 g_W1h[W1_E], g_W1l[W1_E];
__device__ bf16 g_W2h[W1_E], g_W2l[W1_E];
__device__ bf16 g_Qh[QKV_E], g_Ql[QKV_E];
__device__ bf16 g_Kh[QKV_E], g_Kl[QKV_E];
__device__ float g_V[QKV_E];
__device__ bf16 g_VTh[QKV_E], g_VTl[QKV_E];
__device__ float g_P[P_E];
__device__ bf16 g_Ph[P_E], g_Pl[P_E];
__device__ bf16 g_ch[CTX_E], g_cl[CTX_E];
__device__ float g_attn[OUT_E];
__device__ bf16 g_xnh[OUT_E], g_xnl[OUT_E];
__device__ bf16 g_fh[FFH_E], g_fl[FFH_E];

// ---------------------------------------------------------------------------
__device__ __forceinline__ uint32_t s2u(const void* p){
    uint32_t a;
    asm("{ .reg .u64 t; cvta.to.shared.u64 t, %1; cvt.u32.u64 %0, t; }"
        : "=r"(a) : "l"(p));
    return a;
}
__device__ __forceinline__ void split2(float v, bf16& h, bf16& l){
    h = __float2bfloat16(v);
    l = __float2bfloat16(v - __bfloat162float(h));
}

#define CP_COMMIT() asm volatile("cp.async.commit_group;" ::: "memory")
#define CP_WAIT2()  asm volatile("cp.async.wait_group 2;" ::: "memory")
#define CP_WAIT1()  asm volatile("cp.async.wait_group 1;" ::: "memory")
#define CP_WAIT0()  asm volatile("cp.async.wait_group 0;" ::: "memory")

__device__ __forceinline__ void ldm_x4(uint32_t* r, uint32_t a){
    asm volatile("ldmatrix.sync.aligned.m8n8.x4.shared.b16 {%0,%1,%2,%3}, [%4];"
        : "=r"(r[0]), "=r"(r[1]), "=r"(r[2]), "=r"(r[3]) : "r"(a));
}

#define MMA(d, a, b) \
    asm volatile("mma.sync.aligned.m16n8k16.row.col.f32.bf16.bf16.f32 " \
        "{%0,%1,%2,%3}, {%4,%5,%6,%7}, {%8,%9}, {%0,%1,%2,%3};" \
        : "+f"((d)[0]), "+f"((d)[1]), "+f"((d)[2]), "+f"((d)[3]) \
        : "r"((a)[0]), "r"((a)[1]), "r"((a)[2]), "r"((a)[3]), \
          "r"((b)[0]), "r"((b)[1]))

// SMEM stage layout: Ah @0, Al @10240, Bh @20480, Bl @30720; rows padded to 80B.
#define STAGE_B 40960
#define NSTAGE  4

__device__ __forceinline__ void stage_load(
    char* sbase, const bf16* __restrict__ Ah, const bf16* __restrict__ Al,
    const bf16* __restrict__ Bh, const bf16* __restrict__ Bl,
    int m0, int n0, int k0, int lda, int ldb, int tid)
{
#pragma unroll
    for (int t = 0; t < 8; ++t){
        const int q = tid + t * 256;
        const int tile = q >> 9;
        const int rem  = q & 511;
        const int r    = rem >> 2;
        const int c    = rem & 3;
        const bf16* gp;
        if (tile == 0)      gp = Ah + (long)(m0 + r) * lda + k0 + c * 8;
        else if (tile == 1) gp = Al + (long)(m0 + r) * lda + k0 + c * 8;
        else if (tile == 2) gp = Bh + (long)(n0 + r) * ldb + k0 + c * 8;
        else                gp = Bl + (long)(n0 + r) * ldb + k0 + c * 8;
        const uint32_t so = s2u(sbase + tile * 10240 + r * 80 + c * 16);
        asm volatile("cp.async.cg.shared.global [%0], [%1], 16;" :: "r"(so), "l"(gp));
    }
}

__device__ __forceinline__ void stage_mma(uint32_t su, int wm, int wn, int lane,
                                          float (*acc)[4][4])
{
    const int lr = lane & 7, g = lane >> 3;
    const uint32_t aoff = (uint32_t)((((g & 1) * 8 + lr) * 80) + (g >> 1) * 16);
    const uint32_t boff = (uint32_t)((((g >> 1) * 8 + lr) * 80) + (g & 1) * 16);
    const uint32_t uAh = su + (uint32_t)(wm * 80) + aoff;
    const uint32_t uAl = uAh + 10240;
    const uint32_t uBh = su + 20480 + (uint32_t)(wn * 80) + boff;
    const uint32_t uBl = uBh + 10240;

#pragma unroll
    for (int kk = 0; kk < 2; ++kk){
        uint32_t ah[4][4], al[4][4], bh[2][4], bl[2][4];
#pragma unroll
        for (int mi = 0; mi < 4; ++mi) ldm_x4(ah[mi], uAh + mi * 1280 + kk * 32);
#pragma unroll
        for (int j = 0; j < 2; ++j)    ldm_x4(bh[j], uBh + j * 1280 + kk * 32);
#pragma unroll
        for (int mi = 0; mi < 4; ++mi)
#pragma unroll
            for (int ni = 0; ni < 4; ++ni)
                MMA(acc[mi][ni], ah[mi], &bh[ni >> 1][(ni & 1) * 2]);
#pragma unroll
        for (int j = 0; j < 2; ++j)    ldm_x4(bl[j], uBl + j * 1280 + kk * 32);
#pragma unroll
        for (int mi = 0; mi < 4; ++mi)
#pragma unroll
            for (int ni = 0; ni < 4; ++ni)
                MMA(acc[mi][ni], ah[mi], &bl[ni >> 1][(ni & 1) * 2]);
#pragma unroll
        for (int mi = 0; mi < 4; ++mi) ldm_x4(al[mi], uAl + mi * 1280 + kk * 32);
#pragma unroll
        for (int mi = 0; mi < 4; ++mi)
#pragma unroll
            for (int ni = 0; ni < 4; ++ni)
                MMA(acc[mi][ni], al[mi], &bh[ni >> 1][(ni & 1) * 2]);
    }
}

// ---------------------------------------------------------------------------
// HMMA GEMM: C[M,N] = A[M,K] * B[N,K]^T (both K-major bf16 hi/lo), fp32 acc.
// 4-stage cp.async ring, 3-deep prefetch, ONE __syncthreads per stage.
// Safety argument:
//  - wait_group (rem-dependent) drains this thread's stage-ks copies;
//  - the barrier then publishes all threads' stage-ks data before mma(ks);
//  - the new load (stage ks+3) targets buffer (ks-1)&3, whose consumer
//    mma(ks-1) finished before any thread could reach this iteration's
//    barrier (program order), and the load is issued after that barrier.
// EPI: 0=f32 store, 1=f32*scale, 2=GELU->hi/lo, 3=+Res->f32, 4=hi/lo split
// ---------------------------------------------------------------------------
template<int EPI, bool CAUSAL, bool KLIM>
__global__ __launch_bounds__(256) void mm_gemm(
    const bf16* __restrict__ Ah, const bf16* __restrict__ Al,
    const bf16* __restrict__ Bh, const bf16* __restrict__ Bl,
    float* __restrict__ C, bf16* __restrict__ Ch, bf16* __restrict__ Cl,
    const float* __restrict__ Res,
    int K, int lda, int ldb, int ldc,
    long sAb, long sAh_, long sBb, long sBh_, long sCb, long sCh_,
    int Hn, float scale)
{
    const int m0 = blockIdx.y * 128;
    const int n0 = blockIdx.x * 128;
    if (CAUSAL && n0 > m0) return;

    const int z = blockIdx.z, b_ = z / Hn, h_ = z - b_ * Hn;
    Ah += b_*sAb + h_*sAh_;  Al += b_*sAb + h_*sAh_;
    Bh += b_*sBb + h_*sBh_;  Bl += b_*sBb + h_*sBh_;
    const long cOff = b_*sCb + h_*sCh_;

    extern __shared__ char sm[];
    const int tid = threadIdx.x, lane = tid & 31, wid = tid >> 5;
    const int wm = (wid >> 2) * 64, wn = (wid & 3) * 32;

    const int Keff = KLIM ? min(K, m0 + 128) : K;
    const int nst  = Keff >> 5;     // all call sites have nst >= 4

    float acc[4][4][4];
#pragma unroll
    for (int i = 0; i < 4; ++i)
#pragma unroll
        for (int j = 0; j < 4; ++j)
#pragma unroll
            for (int r = 0; r < 4; ++r) acc[i][j][r] = 0.f;

    stage_load(sm, Ah, Al, Bh, Bl, m0, n0, 0, lda, ldb, tid);
    CP_COMMIT();
    stage_load(sm + STAGE_B, Ah, Al, Bh, Bl, m0, n0, 32, lda, ldb, tid);
    CP_COMMIT();
    stage_load(sm + 2 * STAGE_B, Ah, Al, Bh, Bl, m0, n0, 64, lda, ldb, tid);
    CP_COMMIT();

    for (int ks = 0; ks < nst; ++ks){
        const int rem = nst - ks;            // loads still in flight incl. ks
        if (rem > 2)       CP_WAIT2();       // own stage-ks copies done
        else if (rem == 2) CP_WAIT1();
        else               CP_WAIT0();
        __syncthreads();                     // publish stage ks; also orders
                                             // mma(ks-1) before the load below
        if (ks + 3 < nst){
            stage_load(sm + ((ks + 3) & 3) * STAGE_B, Ah, Al, Bh, Bl,
                       m0, n0, (ks + 3) * 32, lda, ldb, tid);
            CP_COMMIT();
        }
        stage_mma(s2u(sm) + (uint32_t)((ks & 3) * STAGE_B), wm, wn, lane, acc);
    }

    // Epilogue: direct global stores (2 fp32 per thread per fragment row)
    const int rbase = m0 + wm + (lane >> 2);
    const int cbase = n0 + wn + (lane & 3) * 2;
#pragma unroll
    for (int mi = 0; mi < 4; ++mi){
#pragma unroll
        for (int ni = 0; ni < 4; ++ni){
#pragma unroll
            for (int half = 0; half < 2; ++half){
                const long r = rbase + mi * 16 + half * 8;
                const long n = cbase + ni * 8;
                const long o = cOff + r * (long)ldc + n;
                float v0 = acc[mi][ni][half * 2];
                float v1 = acc[mi][ni][half * 2 + 1];
                if (EPI == 0){
                    float2 s; s.x = v0; s.y = v1;
                    *reinterpret_cast<float2*>(C + o) = s;
                } else if (EPI == 1){
                    float2 s; s.x = v0 * scale; s.y = v1 * scale;
                    *reinterpret_cast<float2*>(C + o) = s;
                } else if (EPI == 2){
                    const float g0 = 0.5f * v0 * (1.f + erff(v0 * 0.70710678118654752f));
                    const float g1 = 0.5f * v1 * (1.f + erff(v1 * 0.70710678118654752f));
                    bf16 h0, l0, h1, l1;
                    split2(g0, h0, l0); split2(g1, h1, l1);
                    __nv_bfloat162 hh; hh.x = h0; hh.y = h1;
                    __nv_bfloat162 ll; ll.x = l0; ll.y = l1;
                    *reinterpret_cast<__nv_bfloat162*>(Ch + o) = hh;
                    *reinterpret_cast<__nv_bfloat162*>(Cl + o) = ll;
                } else if (EPI == 3){
                    const float2 rv = *reinterpret_cast<const float2*>(Res + o);
                    float2 s; s.x = v0 + rv.x; s.y = v1 + rv.y;
                    *reinterpret_cast<float2*>(C + o) = s;
                } else {
                    bf16 h0, l0, h1, l1;
                    split2(v0, h0, l0); split2(v1, h1, l1);
                    __nv_bfloat162 hh; hh.x = h0; hh.y = h1;
                    __nv_bfloat162 ll; ll.x = l0; ll.y = l1;
                    *reinterpret_cast<__nv_bfloat162*>(Ch + o) = hh;
                    *reinterpret_cast<__nv_bfloat162*>(Cl + o) = ll;
                }
            }
        }
    }
}

// ---------------------------------------------------------------------------
// fused fp32 -> bf16 hi/lo split over 4 arrays (one launch)
// ---------------------------------------------------------------------------
__global__ __launch_bounds__(256) void split4_k(
    const float* __restrict__ X0, bf16* __restrict__ h0, bf16* __restrict__ l0, long n0,
    const float* __restrict__ X1, bf16* __restrict__ h1, bf16* __restrict__ l1, long n1,
    const float* __restrict__ X2, bf16* __restrict__ h2, bf16* __restrict__ l2, long n2,
    const float* __restrict__ X3, bf16* __restrict__ h3, bf16* __restrict__ l3, long n3)
{
    const long tot = n0 + n1 + n2 + n3;
    long i  = blockIdx.x * 256L + threadIdx.x;
    long st = (long)gridDim.x * 256L;
    for (; i < tot; i += st){
        const float* X; bf16 *hp, *lp; long j = i;
        if (j < n0){ X = X0; hp = h0; lp = l0; }
        else if ((j -= n0) < n1){ X = X1; hp = h1; lp = l1; }
        else if ((j -= n1) < n2){ X = X2; hp = h2; lp = l2; }
        else { j -= n2; X = X3; hp = h3; lp = l3; }
        bf16 h, l; split2(X[j], h, l);
        hp[j] = h; lp[j] = l;
    }
}

// transpose + split: per z, X[R,C] row-major -> out[C,R] hi/lo
__global__ __launch_bounds__(256) void split_t_k(const float* __restrict__ X,
                                                 bf16* __restrict__ hi,
                                                 bf16* __restrict__ lo,
                                                 int R, int C, long sX, long sO)
{
    __shared__ float t[32][33];
    const float* Xz = X + (long)blockIdx.z * sX;
    const int c0 = blockIdx.x * 32, r0 = blockIdx.y * 32;
    const int tx = threadIdx.x & 31, ty = threadIdx.x >> 5;
#pragma unroll
    for (int i = 0; i < 32; i += 8)
        t[ty + i][tx] = Xz[(long)(r0 + ty + i) * C + c0 + tx];
    __syncthreads();
#pragma unroll
    for (int i = 0; i < 32; i += 8){
        const float v = t[tx][ty + i];
        const long o = (long)blockIdx.z * sO + (long)(c0 + ty + i) * R + r0 + tx;
        bf16 h, l; split2(v, h, l);
        hi[o] = h; lo[o] = l;
    }
}

// ---------------------------------------------------------------------------
// Causal softmax: fp32 scores row -> bf16 hi/lo probs (zero-padded to 128)
// ---------------------------------------------------------------------------
__global__ __launch_bounds__(256) void softmax_k(const float* __restrict__ P,
                                                 bf16* __restrict__ Ph,
                                                 bf16* __restrict__ Pl)
{
    const long r  = blockIdx.x;
    const int  q  = (int)(r % SS);
    const float* row = P + r * (long)SS;
    const int len = q + 1;
    const int t   = threadIdx.x;

    float v[8];
    float mx = -INFINITY;
#pragma unroll
    for (int i = 0; i < 8; ++i){
        const int k = t + i * 256;
        v[i] = (k < len) ? row[k] : -INFINITY;
        mx = fmaxf(mx, v[i]);
    }
    __shared__ float red[256];
    red[t] = mx; __syncthreads();
    for (int s = 128; s > 0; s >>= 1){
        if (t < s) red[t] = fmaxf(red[t], red[t + s]);
        __syncthreads();
    }
    mx = red[0]; __syncthreads();

    float sum = 0.f;
#pragma unroll
    for (int i = 0; i < 8; ++i){
        const int k = t + i * 256;
        if (k < len){ v[i] = expf(v[i] - mx); sum += v[i]; }
        else v[i] = 0.f;
    }
    red[t] = sum; __syncthreads();
    for (int s = 128; s > 0; s >>= 1){
        if (t < s) red[t] += red[t + s];
        __syncthreads();
    }
    const float inv = 1.f / red[0];

    const int zlen = (q / 128 + 1) * 128;
    bf16* ph = Ph + r * (long)SS;
    bf16* pl = Pl + r * (long)SS;
#pragma unroll
    for (int i = 0; i < 8; ++i){
        const int k = t + i * 256;
        if (k < zlen){
            bf16 h, l; split2(v[i] * inv, h, l);
            ph[k] = h; pl[k] = l;
        }
    }
}

// LayerNorm (no affine) -> bf16 hi/lo
__global__ __launch_bounds__(256) void ln_k(const float* __restrict__ X,
                                            bf16* __restrict__ Yh,
                                            bf16* __restrict__ Yl)
{
    const long r = blockIdx.x;
    const float* x = X + r * (long)DD;
    const int t = threadIdx.x;

    float s = 0.f, s2 = 0.f;
#pragma unroll
    for (int i = 0; i < 3; ++i){
        const float v = x[t + i * 256];
        s += v; s2 += v * v;
    }
    __shared__ float rs[256], rs2[256];
    rs[t] = s; rs2[t] = s2; __syncthreads();
    for (int st = 128; st > 0; st >>= 1){
        if (t < st){ rs[t] += rs[t + st]; rs2[t] += rs2[t + st]; }
        __syncthreads();
    }
    const float mu   = rs[0] * (1.f / DD);
    const float var  = rs2[0] * (1.f / DD) - mu * mu;
    const float rstd = rsqrtf(var + 1e-5f);
#pragma unroll
    for (int i = 0; i < 3; ++i){
        const int k = t + i * 256;
        bf16 h, l; split2((x[k] - mu) * rstd, h, l);
        Yh[r * (long)DD + k] = h; Yl[r * (long)DD + k] = l;
    }
}

// ---------------------------------------------------------------------------
extern "C" void kernel_launch(void* const* d_in, const int* in_sizes, int n_in,
                              void* d_out, int out_size)
{
    const float* x  = (const float*)d_in[0];
    const float* Wq = (const float*)d_in[1];
    const float* Wk = (const float*)d_in[2];
    const float* Wv = (const float*)d_in[3];
    const float* Wo = (const float*)d_in[4];
    const float* W1 = (const float*)d_in[5];
    const float* W2 = (const float*)d_in[6];
    float* out = (float*)d_out;

    bf16 *xh,*xl,*WqTh,*WqTl,*WkTh,*WkTl,*WvTh,*WvTl,*Woh,*Wol,*W1h,*W1l,*W2h,*W2l;
    bf16 *Qh,*Ql,*Kh,*Kl,*VTh,*VTl,*Ph,*Pl,*ch,*cl,*xnh,*xnl,*fh,*fl;
    float *V,*P,*attn;
    cudaGetSymbolAddress((void**)&xh, g_xh);   cudaGetSymbolAddress((void**)&xl, g_xl);
    cudaGetSymbolAddress((void**)&WqTh, g_WqTh); cudaGetSymbolAddress((void**)&WqTl, g_WqTl);
    cudaGetSymbolAddress((void**)&WkTh, g_WkTh); cudaGetSymbolAddress((void**)&WkTl, g_WkTl);
    cudaGetSymbolAddress((void**)&WvTh, g_WvTh); cudaGetSymbolAddress((void**)&WvTl, g_WvTl);
    cudaGetSymbolAddress((void**)&Woh, g_Woh); cudaGetSymbolAddress((void**)&Wol, g_Wol);
    cudaGetSymbolAddress((void**)&W1h, g_W1h); cudaGetSymbolAddress((void**)&W1l, g_W1l);
    cudaGetSymbolAddress((void**)&W2h, g_W2h); cudaGetSymbolAddress((void**)&W2l, g_W2l);
    cudaGetSymbolAddress((void**)&Qh, g_Qh);   cudaGetSymbolAddress((void**)&Ql, g_Ql);
    cudaGetSymbolAddress((void**)&Kh, g_Kh);   cudaGetSymbolAddress((void**)&Kl, g_Kl);
    cudaGetSymbolAddress((void**)&V, g_V);
    cudaGetSymbolAddress((void**)&VTh, g_VTh); cudaGetSymbolAddress((void**)&VTl, g_VTl);
    cudaGetSymbolAddress((void**)&P, g_P);
    cudaGetSymbolAddress((void**)&Ph, g_Ph);   cudaGetSymbolAddress((void**)&Pl, g_Pl);
    cudaGetSymbolAddress((void**)&ch, g_ch);   cudaGetSymbolAddress((void**)&cl, g_cl);
    cudaGetSymbolAddress((void**)&attn, g_attn);
    cudaGetSymbolAddress((void**)&xnh, g_xnh); cudaGetSymbolAddress((void**)&xnl, g_xnl);
    cudaGetSymbolAddress((void**)&fh, g_fh);   cudaGetSymbolAddress((void**)&fl, g_fl);

    const int SMEMB = NSTAGE * STAGE_B;   // 163840 (1 CTA/SM, deep prefetch)
    cudaFuncSetAttribute(mm_gemm<4,false,false>, cudaFuncAttributeMaxDynamicSharedMemorySize, SMEMB);
    cudaFuncSetAttribute(mm_gemm<0,false,false>, cudaFuncAttributeMaxDynamicSharedMemorySize, SMEMB);
    cudaFuncSetAttribute(mm_gemm<1,true ,false>, cudaFuncAttributeMaxDynamicSharedMemorySize, SMEMB);
    cudaFuncSetAttribute(mm_gemm<4,false,true >, cudaFuncAttributeMaxDynamicSharedMemorySize, SMEMB);
    cudaFuncSetAttribute(mm_gemm<2,false,false>, cudaFuncAttributeMaxDynamicSharedMemorySize, SMEMB);
    cudaFuncSetAttribute(mm_gemm<3,false,false>, cudaFuncAttributeMaxDynamicSharedMemorySize, SMEMB);

    const long sSD  = (long)SS*DD;
    const long sBSD = (long)HH*SS*DD;

    // --- prep: fused flat splits + transposed weight splits ---
    split4_k<<<8192, 256>>>(x, xh, xl, OUT_E,
                            Wo, Woh, Wol, WO_E,
                            W1, W1h, W1l, W1_E,
                            W2, W2h, W2l, W1_E);
    {
        dim3 g(DD/32, DD/32, HH);
        split_t_k<<<g, 256>>>(Wq, WqTh, WqTl, DD, DD, (long)DD*DD, (long)DD*DD);
        split_t_k<<<g, 256>>>(Wk, WkTh, WkTl, DD, DD, (long)DD*DD, (long)DD*DD);
        split_t_k<<<g, 256>>>(Wv, WvTh, WvTl, DD, DD, (long)DD*DD, (long)DD*DD);
    }

    // --- Q, K projections (split output), V projection (fp32) ---
    {
        dim3 g(DD/128, SS/128, BB*HH);
        mm_gemm<4,false,false><<<g, 256, SMEMB>>>(
            xh, xl, WqTh, WqTl, nullptr, Qh, Ql, nullptr,
            DD, DD, DD, DD, sSD, 0L, 0L, (long)DD*DD, sBSD, sSD, HH, 1.f);
        mm_gemm<4,false,false><<<g, 256, SMEMB>>>(
            xh, xl, WkTh, WkTl, nullptr, Kh, Kl, nullptr,
            DD, DD, DD, DD, sSD, 0L, 0L, (long)DD*DD, sBSD, sSD, HH, 1.f);
        mm_gemm<0,false,false><<<g, 256, SMEMB>>>(
            xh, xl, WvTh, WvTl, V, nullptr, nullptr, nullptr,
            DD, DD, DD, DD, sSD, 0L, 0L, (long)DD*DD, sBSD, sSD, HH, 1.f);
    }
    // V -> V^T hi/lo (per b,h: [2048,768] -> [768,2048])
    {
        dim3 g(DD/32, SS/32, BB*HH);
        split_t_k<<<g, 256>>>(V, VTh, VTl, SS, DD, sSD, sSD);
    }
    // --- scores = (Q K^T)/sqrt(D), causal tile skip, fp32 out ---
    {
        dim3 g(SS/128, SS/128, BB*HH);
        mm_gemm<1,true,false><<<g, 256, SMEMB>>>(
            Qh, Ql, Kh, Kl, P, nullptr, nullptr, nullptr,
            DD, DD, DD, SS, sBSD, sSD, sBSD, sSD,
            (long)HH*SS*SS, (long)SS*SS, HH, rsqrtf((float)DD));
    }
    // --- softmax -> hi/lo ---
    softmax_k<<<BB*HH*SS, 256>>>(P, Ph, Pl);
    // --- ctx = P V (K-limited), split output scattered to [B,S,H*D] ---
    {
        dim3 g(DD/128, SS/128, BB*HH);
        mm_gemm<4,false,true><<<g, 256, SMEMB>>>(
            Ph, Pl, VTh, VTl, nullptr, ch, cl, nullptr,
            SS, SS, SS, HH*DD,
            (long)HH*SS*SS, (long)SS*SS, (long)HH*DD*SS, (long)DD*SS,
            (long)SS*HH*DD, (long)DD, HH, 1.f);
    }
    // --- attn = ctx @ Wo^T (fp32) ---
    {
        dim3 g(DD/128, (BB*SS)/128, 1);
        mm_gemm<0,false,false><<<g, 256, SMEMB>>>(
            ch, cl, Woh, Wol, attn, nullptr, nullptr, nullptr,
            HH*DD, HH*DD, HH*DD, DD, 0L,0L,0L,0L,0L,0L, 1, 1.f);
    }
    // --- LN -> hi/lo ---
    ln_k<<<BB*SS, 256>>>(attn, xnh, xnl);
    // --- FFN1: GELU(xn @ W1^T) -> hi/lo ---
    {
        dim3 g(FF/128, (BB*SS)/128, 1);
        mm_gemm<2,false,false><<<g, 256, SMEMB>>>(
            xnh, xnl, W1h, W1l, nullptr, fh, fl, nullptr,
            DD, DD, DD, FF, 0L,0L,0L,0L,0L,0L, 1, 1.f);
    }
    // --- FFN2: out = attn + ffh @ W2^T ---
    {
        dim3 g(DD/128, (BB*SS)/128, 1);
        mm_gemm<3,false,false><<<g, 256, SMEMB>>>(
            fh, fl, W2h, W2l, out, nullptr, nullptr, attn,
            FF, FF, FF, DD, 0L,0L,0L,0L,0L,0L, 1, 1.f);
    }
}

// round 16
// speedup vs baseline: 1.3557x; 1.0040x over previous
#include <cuda_runtime.h>
#include <cuda_bf16.h>
#include <math.h>
#include <stdint.h>

#define BB 2
#define SS 2048
#define HH 12
#define DD 768
#define FF (4*DD)

typedef __nv_bfloat16 bf16;

constexpr long QKV_E = (long)BB*HH*SS*DD;
constexpr long P_E   = (long)BB*HH*SS*SS;
constexpr long CTX_E = (long)BB*SS*HH*DD;
constexpr long OUT_E = (long)BB*SS*DD;
constexpr long FFH_E = (long)BB*SS*FF;
constexpr long WQ_E  = (long)HH*DD*DD;
constexpr long WO_E  = (long)DD*HH*DD;
constexpr long W1_E  = (long)FF*DD;

// ---- scratch (__device__ globals; no allocation allowed) ----
__device__ bf16 g_xh[OUT_E], g_xl[OUT_E];
__device__ bf16 g_WqTh[WQ_E], g_WqTl[WQ_E];
__device__ bf16 g_WkTh[WQ_E], g_WkTl[WQ_E];
__device__ bf16 g_WvTh[WQ_E], g_WvTl[WQ_E];
__device__ bf16 g_Woh[WO_E], g_Wol[WO_E];
__device__ bf16 g_W1h[W1_E], g_W1l[W1_E];
__device__ bf16 g_W2h[W1_E], g_W2l[W1_E];
__device__ bf16 g_Qh[QKV_E], g_Ql[QKV_E];
__device__ bf16 g_Kh[QKV_E], g_Kl[QKV_E];
__device__ bf16 g_VTh[QKV_E], g_VTl[QKV_E];
__device__ float g_P[P_E];
__device__ bf16 g_Ph[P_E], g_Pl[P_E];
__device__ bf16 g_ch[CTX_E], g_cl[CTX_E];
__device__ float g_attn[OUT_E];
__device__ bf16 g_xnh[OUT_E], g_xnl[OUT_E];
__device__ bf16 g_fh[FFH_E], g_fl[FFH_E];

// ---------------------------------------------------------------------------
__device__ __forceinline__ uint32_t s2u(const void* p){
    uint32_t a;
    asm("{ .reg .u64 t; cvta.to.shared.u64 t, %1; cvt.u32.u64 %0, t; }"
        : "=r"(a) : "l"(p));
    return a;
}
__device__ __forceinline__ void split2(float v, bf16& h, bf16& l){
    h = __float2bfloat16(v);
    l = __float2bfloat16(v - __bfloat162float(h));
}

#define CP_COMMIT() asm volatile("cp.async.commit_group;" ::: "memory")
#define CP_WAIT2()  asm volatile("cp.async.wait_group 2;" ::: "memory")
#define CP_WAIT1()  asm volatile("cp.async.wait_group 1;" ::: "memory")
#define CP_WAIT0()  asm volatile("cp.async.wait_group 0;" ::: "memory")

__device__ __forceinline__ void ldm_x4(uint32_t* r, uint32_t a){
    asm volatile("ldmatrix.sync.aligned.m8n8.x4.shared.b16 {%0,%1,%2,%3}, [%4];"
        : "=r"(r[0]), "=r"(r[1]), "=r"(r[2]), "=r"(r[3]) : "r"(a));
}

#define MMA(d, a, b) \
    asm volatile("mma.sync.aligned.m16n8k16.row.col.f32.bf16.bf16.f32 " \
        "{%0,%1,%2,%3}, {%4,%5,%6,%7}, {%8,%9}, {%0,%1,%2,%3};" \
        : "+f"((d)[0]), "+f"((d)[1]), "+f"((d)[2]), "+f"((d)[3]) \
        : "r"((a)[0]), "r"((a)[1]), "r"((a)[2]), "r"((a)[3]), \
          "r"((b)[0]), "r"((b)[1]))

// SMEM stage layout: Ah @0, Al @10240, Bh @20480, Bl @30720; rows padded to 80B.
#define STAGE_B 40960
#define NSTAGE  4

__device__ __forceinline__ void stage_load(
    char* sbase, const bf16* __restrict__ Ah, const bf16* __restrict__ Al,
    const bf16* __restrict__ Bh, const bf16* __restrict__ Bl,
    int m0, int n0, int k0, int lda, int ldb, int tid)
{
#pragma unroll
    for (int t = 0; t < 8; ++t){
        const int q = tid + t * 256;
        const int tile = q >> 9;
        const int rem  = q & 511;
        const int r    = rem >> 2;
        const int c    = rem & 3;
        const bf16* gp;
        if (tile == 0)      gp = Ah + (long)(m0 + r) * lda + k0 + c * 8;
        else if (tile == 1) gp = Al + (long)(m0 + r) * lda + k0 + c * 8;
        else if (tile == 2) gp = Bh + (long)(n0 + r) * ldb + k0 + c * 8;
        else                gp = Bl + (long)(n0 + r) * ldb + k0 + c * 8;
        const uint32_t so = s2u(sbase + tile * 10240 + r * 80 + c * 16);
        asm volatile("cp.async.cg.shared.global [%0], [%1], 16;" :: "r"(so), "l"(gp));
    }
}

__device__ __forceinline__ void stage_mma(uint32_t su, int wm, int wn, int lane,
                                          float (*acc)[4][4])
{
    const int lr = lane & 7, g = lane >> 3;
    const uint32_t aoff = (uint32_t)((((g & 1) * 8 + lr) * 80) + (g >> 1) * 16);
    const uint32_t boff = (uint32_t)((((g >> 1) * 8 + lr) * 80) + (g & 1) * 16);
    const uint32_t uAh = su + (uint32_t)(wm * 80) + aoff;
    const uint32_t uAl = uAh + 10240;
    const uint32_t uBh = su + 20480 + (uint32_t)(wn * 80) + boff;
    const uint32_t uBl = uBh + 10240;

#pragma unroll
    for (int kk = 0; kk < 2; ++kk){
        uint32_t ah[4][4], al[4][4], bh[2][4], bl[2][4];
#pragma unroll
        for (int mi = 0; mi < 4; ++mi) ldm_x4(ah[mi], uAh + mi * 1280 + kk * 32);
#pragma unroll
        for (int j = 0; j < 2; ++j)    ldm_x4(bh[j], uBh + j * 1280 + kk * 32);
#pragma unroll
        for (int mi = 0; mi < 4; ++mi)
#pragma unroll
            for (int ni = 0; ni < 4; ++ni)
                MMA(acc[mi][ni], ah[mi], &bh[ni >> 1][(ni & 1) * 2]);
#pragma unroll
        for (int j = 0; j < 2; ++j)    ldm_x4(bl[j], uBl + j * 1280 + kk * 32);
#pragma unroll
        for (int mi = 0; mi < 4; ++mi)
#pragma unroll
            for (int ni = 0; ni < 4; ++ni)
                MMA(acc[mi][ni], ah[mi], &bl[ni >> 1][(ni & 1) * 2]);
#pragma unroll
        for (int mi = 0; mi < 4; ++mi) ldm_x4(al[mi], uAl + mi * 1280 + kk * 32);
#pragma unroll
        for (int mi = 0; mi < 4; ++mi)
#pragma unroll
            for (int ni = 0; ni < 4; ++ni)
                MMA(acc[mi][ni], al[mi], &bh[ni >> 1][(ni & 1) * 2]);
    }
}

// ---------------------------------------------------------------------------
// HMMA GEMM: C[M,N] = A[M,K] * B[N,K]^T (both K-major bf16 hi/lo), fp32 acc.
// 4-stage cp.async ring, 3-deep prefetch, ONE __syncthreads per stage.
// EPI: 0=f32 store, 1=f32*scale, 2=GELU->hi/lo, 3=+Res->f32, 4=hi/lo split,
//      5=TRANSPOSED hi/lo split (C^T stored, ldc = transposed row stride)
// ---------------------------------------------------------------------------
template<int EPI, bool CAUSAL, bool KLIM>
__global__ __launch_bounds__(256) void mm_gemm(
    const bf16* __restrict__ Ah, const bf16* __restrict__ Al,
    const bf16* __restrict__ Bh, const bf16* __restrict__ Bl,
    float* __restrict__ C, bf16* __restrict__ Ch, bf16* __restrict__ Cl,
    const float* __restrict__ Res,
    int K, int lda, int ldb, int ldc,
    long sAb, long sAh_, long sBb, long sBh_, long sCb, long sCh_,
    int Hn, float scale)
{
    const int m0 = blockIdx.y * 128;
    const int n0 = blockIdx.x * 128;
    if (CAUSAL && n0 > m0) return;

    const int z = blockIdx.z, b_ = z / Hn, h_ = z - b_ * Hn;
    Ah += b_*sAb + h_*sAh_;  Al += b_*sAb + h_*sAh_;
    Bh += b_*sBb + h_*sBh_;  Bl += b_*sBb + h_*sBh_;
    const long cOff = b_*sCb + h_*sCh_;

    extern __shared__ char sm[];
    const int tid = threadIdx.x, lane = tid & 31, wid = tid >> 5;
    const int wm = (wid >> 2) * 64, wn = (wid & 3) * 32;

    const int Keff = KLIM ? min(K, m0 + 128) : K;
    const int nst  = Keff >> 5;     // all call sites have nst >= 4

    float acc[4][4][4];
#pragma unroll
    for (int i = 0; i < 4; ++i)
#pragma unroll
        for (int j = 0; j < 4; ++j)
#pragma unroll
            for (int r = 0; r < 4; ++r) acc[i][j][r] = 0.f;

    stage_load(sm, Ah, Al, Bh, Bl, m0, n0, 0, lda, ldb, tid);
    CP_COMMIT();
    stage_load(sm + STAGE_B, Ah, Al, Bh, Bl, m0, n0, 32, lda, ldb, tid);
    CP_COMMIT();
    stage_load(sm + 2 * STAGE_B, Ah, Al, Bh, Bl, m0, n0, 64, lda, ldb, tid);
    CP_COMMIT();

    for (int ks = 0; ks < nst; ++ks){
        const int rem = nst - ks;            // loads still in flight incl. ks
        if (rem > 2)       CP_WAIT2();       // own stage-ks copies done
        else if (rem == 2) CP_WAIT1();
        else               CP_WAIT0();
        __syncthreads();                     // publish stage ks; also orders
                                             // mma(ks-1) before the load below
        if (ks + 3 < nst){
            stage_load(sm + ((ks + 3) & 3) * STAGE_B, Ah, Al, Bh, Bl,
                       m0, n0, (ks + 3) * 32, lda, ldb, tid);
            CP_COMMIT();
        }
        stage_mma(s2u(sm) + (uint32_t)((ks & 3) * STAGE_B), wm, wn, lane, acc);
    }

    if (EPI == 5){
        // Transposed hi/lo epilogue: stage fp32 tile in smem, store C^T.
        __syncthreads();                     // all warps done reading smem
        float* smf = (float*)sm;             // 128 x 129 fp32 = 66 KB
#pragma unroll
        for (int mi = 0; mi < 4; ++mi)
#pragma unroll
            for (int ni = 0; ni < 4; ++ni)
#pragma unroll
                for (int half = 0; half < 2; ++half){
                    const int rl = wm + mi * 16 + half * 8 + (lane >> 2);
                    const int nl = wn + ni * 8 + (lane & 3) * 2;
                    smf[rl * 129 + nl]     = acc[mi][ni][half * 2];
                    smf[rl * 129 + nl + 1] = acc[mi][ni][half * 2 + 1];
                }
        __syncthreads();
#pragma unroll 4
        for (int it = 0; it < 32; ++it){
            const int idx = tid + it * 256;          // 8192 = 128n x 64 mpairs
            const int n  = idx >> 6;                 // 0..127
            const int m2 = (idx & 63) * 2;           // 0..126 even
            const float v0 = smf[m2 * 129 + n];
            const float v1 = smf[(m2 + 1) * 129 + n];
            bf16 h0, l0, h1, l1;
            split2(v0, h0, l0); split2(v1, h1, l1);
            __nv_bfloat162 hh; hh.x = h0; hh.y = h1;
            __nv_bfloat162 ll; ll.x = l0; ll.y = l1;
            const long o = cOff + (long)(n0 + n) * ldc + m0 + m2;
            *reinterpret_cast<__nv_bfloat162*>(Ch + o) = hh;
            *reinterpret_cast<__nv_bfloat162*>(Cl + o) = ll;
        }
        return;
    }

    // Epilogue: direct global stores (2 fp32 per thread per fragment row)
    const int rbase = m0 + wm + (lane >> 2);
    const int cbase = n0 + wn + (lane & 3) * 2;
#pragma unroll
    for (int mi = 0; mi < 4; ++mi){
#pragma unroll
        for (int ni = 0; ni < 4; ++ni){
#pragma unroll
            for (int half = 0; half < 2; ++half){
                const long r = rbase + mi * 16 + half * 8;
                const long n = cbase + ni * 8;
                const long o = cOff + r * (long)ldc + n;
                float v0 = acc[mi][ni][half * 2];
                float v1 = acc[mi][ni][half * 2 + 1];
                if (EPI == 0){
                    float2 s; s.x = v0; s.y = v1;
                    *reinterpret_cast<float2*>(C + o) = s;
                } else if (EPI == 1){
                    float2 s; s.x = v0 * scale; s.y = v1 * scale;
                    *reinterpret_cast<float2*>(C + o) = s;
                } else if (EPI == 2){
                    const float g0 = 0.5f * v0 * (1.f + erff(v0 * 0.70710678118654752f));
                    const float g1 = 0.5f * v1 * (1.f + erff(v1 * 0.70710678118654752f));
                    bf16 h0, l0, h1, l1;
                    split2(g0, h0, l0); split2(g1, h1, l1);
                    __nv_bfloat162 hh; hh.x = h0; hh.y = h1;
                    __nv_bfloat162 ll; ll.x = l0; ll.y = l1;
                    *reinterpret_cast<__nv_bfloat162*>(Ch + o) = hh;
                    *reinterpret_cast<__nv_bfloat162*>(Cl + o) = ll;
                } else if (EPI == 3){
                    const float2 rv = *reinterpret_cast<const float2*>(Res + o);
                    float2 s; s.x = v0 + rv.x; s.y = v1 + rv.y;
                    *reinterpret_cast<float2*>(C + o) = s;
                } else {
                    bf16 h0, l0, h1, l1;
                    split2(v0, h0, l0); split2(v1, h1, l1);
                    __nv_bfloat162 hh; hh.x = h0; hh.y = h1;
                    __nv_bfloat162 ll; ll.x = l0; ll.y = l1;
                    *reinterpret_cast<__nv_bfloat162*>(Ch + o) = hh;
                    *reinterpret_cast<__nv_bfloat162*>(Cl + o) = ll;
                }
            }
        }
    }
}

// ---------------------------------------------------------------------------
// fused fp32 -> bf16 hi/lo split over 4 arrays (one launch)
// ---------------------------------------------------------------------------
__global__ __launch_bounds__(256) void split4_k(
    const float* __restrict__ X0, bf16* __restrict__ h0, bf16* __restrict__ l0, long n0,
    const float* __restrict__ X1, bf16* __restrict__ h1, bf16* __restrict__ l1, long n1,
    const float* __restrict__ X2, bf16* __restrict__ h2, bf16* __restrict__ l2, long n2,
    const float* __restrict__ X3, bf16* __restrict__ h3, bf16* __restrict__ l3, long n3)
{
    const long tot = n0 + n1 + n2 + n3;
    long i  = blockIdx.x * 256L + threadIdx.x;
    long st = (long)gridDim.x * 256L;
    for (; i < tot; i += st){
        const float* X; bf16 *hp, *lp; long j = i;
        if (j < n0){ X = X0; hp = h0; lp = l0; }
        else if ((j -= n0) < n1){ X = X1; hp = h1; lp = l1; }
        else if ((j -= n1) < n2){ X = X2; hp = h2; lp = l2; }
        else { j -= n2; X = X3; hp = h3; lp = l3; }
        bf16 h, l; split2(X[j], h, l);
        hp[j] = h; lp[j] = l;
    }
}

// transpose + split: per z, X[R,C] row-major -> out[C,R] hi/lo (weights prep)
__global__ __launch_bounds__(256) void split_t_k(const float* __restrict__ X,
                                                 bf16* __restrict__ hi,
                                                 bf16* __restrict__ lo,
                                                 int R, int C, long sX, long sO)
{
    __shared__ float t[32][33];
    const float* Xz = X + (long)blockIdx.z * sX;
    const int c0 = blockIdx.x * 32, r0 = blockIdx.y * 32;
    const int tx = threadIdx.x & 31, ty = threadIdx.x >> 5;
#pragma unroll
    for (int i = 0; i < 32; i += 8)
        t[ty + i][tx] = Xz[(long)(r0 + ty + i) * C + c0 + tx];
    __syncthreads();
#pragma unroll
    for (int i = 0; i < 32; i += 8){
        const float v = t[tx][ty + i];
        const long o = (long)blockIdx.z * sO + (long)(c0 + ty + i) * R + r0 + tx;
        bf16 h, l; split2(v, h, l);
        hi[o] = h; lo[o] = l;
    }
}

// ---------------------------------------------------------------------------
// Causal softmax: fp32 scores -> bf16 hi/lo probs (zero-padded to 128).
// 512 threads, one float4 per thread, predicated loads/stores at the causal
// boundary (halves traffic on average), shuffle reductions.
// ---------------------------------------------------------------------------
__global__ __launch_bounds__(512) void softmax_k(const float* __restrict__ P,
                                                 bf16* __restrict__ Ph,
                                                 bf16* __restrict__ Pl)
{
    const long r  = blockIdx.x;
    const int  q  = (int)(r % SS);
    const int  len = q + 1;
    const float* row = P + r * (long)SS;
    const int t = threadIdx.x, lane = t & 31, wd = t >> 5;
    const int k0 = t * 4;

    float a0 = -INFINITY, a1 = -INFINITY, a2 = -INFINITY, a3 = -INFINITY;
    if (k0 < len){
        const float4 v = *reinterpret_cast<const float4*>(row + k0);
        a0 = v.x;
        a1 = (k0 + 1 < len) ? v.y : -INFINITY;
        a2 = (k0 + 2 < len) ? v.z : -INFINITY;
        a3 = (k0 + 3 < len) ? v.w : -INFINITY;
    }
    float mx = fmaxf(fmaxf(a0, a1), fmaxf(a2, a3));
#pragma unroll
    for (int o = 16; o; o >>= 1) mx = fmaxf(mx, __shfl_xor_sync(0xffffffffu, mx, o));

    __shared__ float s1[16], s2[16];
    if (lane == 0) s1[wd] = mx;
    __syncthreads();
    if (t < 32){
        float z = (t < 16) ? s1[t] : -INFINITY;
#pragma unroll
        for (int o = 8; o; o >>= 1) z = fmaxf(z, __shfl_xor_sync(0xffffffffu, z, o));
        if (t == 0) s1[0] = z;
    }
    __syncthreads();
    mx = s1[0];

    float e0 = 0.f, e1 = 0.f, e2 = 0.f, e3 = 0.f;
    if (k0     < len) e0 = expf(a0 - mx);
    if (k0 + 1 < len) e1 = expf(a1 - mx);
    if (k0 + 2 < len) e2 = expf(a2 - mx);
    if (k0 + 3 < len) e3 = expf(a3 - mx);
    float sum = (e0 + e1) + (e2 + e3);
#pragma unroll
    for (int o = 16; o; o >>= 1) sum += __shfl_xor_sync(0xffffffffu, sum, o);
    if (lane == 0) s2[wd] = sum;
    __syncthreads();
    if (t < 32){
        float z = (t < 16) ? s2[t] : 0.f;
#pragma unroll
        for (int o = 8; o; o >>= 1) z += __shfl_xor_sync(0xffffffffu, z, o);
        if (t == 0) s2[0] = z;
    }
    __syncthreads();
    const float inv = 1.f / s2[0];

    const int zlen = (q / 128 + 1) * 128;   // 128-block zero fill
    if (k0 < zlen){
        bf16 h0,l0,h1,l1,h2,l2,h3,l3;
        split2(e0 * inv, h0, l0); split2(e1 * inv, h1, l1);
        split2(e2 * inv, h2, l2); split2(e3 * inv, h3, l3);
        const long o = r * (long)SS + k0;
        __nv_bfloat162 p01; p01.x = h0; p01.y = h1;
        __nv_bfloat162 p23; p23.x = h2; p23.y = h3;
        __nv_bfloat162 q01; q01.x = l0; q01.y = l1;
        __nv_bfloat162 q23; q23.x = l2; q23.y = l3;
        *reinterpret_cast<__nv_bfloat162*>(Ph + o)     = p01;
        *reinterpret_cast<__nv_bfloat162*>(Ph + o + 2) = p23;
        *reinterpret_cast<__nv_bfloat162*>(Pl + o)     = q01;
        *reinterpret_cast<__nv_bfloat162*>(Pl + o + 2) = q23;
    }
}

// LayerNorm (no affine) -> bf16 hi/lo
__global__ __launch_bounds__(256) void ln_k(const float* __restrict__ X,
                                            bf16* __restrict__ Yh,
                                            bf16* __restrict__ Yl)
{
    const long r = blockIdx.x;
    const float* x = X + r * (long)DD;
    const int t = threadIdx.x;

    float s = 0.f, s2 = 0.f;
#pragma unroll
    for (int i = 0; i < 3; ++i){
        const float v = x[t + i * 256];
        s += v; s2 += v * v;
    }
    __shared__ float rs[256], rs2[256];
    rs[t] = s; rs2[t] = s2; __syncthreads();
    for (int st = 128; st > 0; st >>= 1){
        if (t < st){ rs[t] += rs[t + st]; rs2[t] += rs2[t + st]; }
        __syncthreads();
    }
    const float mu   = rs[0] * (1.f / DD);
    const float var  = rs2[0] * (1.f / DD) - mu * mu;
    const float rstd = rsqrtf(var + 1e-5f);
#pragma unroll
    for (int i = 0; i < 3; ++i){
        const int k = t + i * 256;
        bf16 h, l; split2((x[k] - mu) * rstd, h, l);
        Yh[r * (long)DD + k] = h; Yl[r * (long)DD + k] = l;
    }
}

// ---------------------------------------------------------------------------
extern "C" void kernel_launch(void* const* d_in, const int* in_sizes, int n_in,
                              void* d_out, int out_size)
{
    const float* x  = (const float*)d_in[0];
    const float* Wq = (const float*)d_in[1];
    const float* Wk = (const float*)d_in[2];
    const float* Wv = (const float*)d_in[3];
    const float* Wo = (const float*)d_in[4];
    const float* W1 = (const float*)d_in[5];
    const float* W2 = (const float*)d_in[6];
    float* out = (float*)d_out;

    bf16 *xh,*xl,*WqTh,*WqTl,*WkTh,*WkTl,*WvTh,*WvTl,*Woh,*Wol,*W1h,*W1l,*W2h,*W2l;
    bf16 *Qh,*Ql,*Kh,*Kl,*VTh,*VTl,*Ph,*Pl,*ch,*cl,*xnh,*xnl,*fh,*fl;
    float *P,*attn;
    cudaGetSymbolAddress((void**)&xh, g_xh);   cudaGetSymbolAddress((void**)&xl, g_xl);
    cudaGetSymbolAddress((void**)&WqTh, g_WqTh); cudaGetSymbolAddress((void**)&WqTl, g_WqTl);
    cudaGetSymbolAddress((void**)&WkTh, g_WkTh); cudaGetSymbolAddress((void**)&WkTl, g_WkTl);
    cudaGetSymbolAddress((void**)&WvTh, g_WvTh); cudaGetSymbolAddress((void**)&WvTl, g_WvTl);
    cudaGetSymbolAddress((void**)&Woh, g_Woh); cudaGetSymbolAddress((void**)&Wol, g_Wol);
    cudaGetSymbolAddress((void**)&W1h, g_W1h); cudaGetSymbolAddress((void**)&W1l, g_W1l);
    cudaGetSymbolAddress((void**)&W2h, g_W2h); cudaGetSymbolAddress((void**)&W2l, g_W2l);
    cudaGetSymbolAddress((void**)&Qh, g_Qh);   cudaGetSymbolAddress((void**)&Ql, g_Ql);
    cudaGetSymbolAddress((void**)&Kh, g_Kh);   cudaGetSymbolAddress((void**)&Kl, g_Kl);
    cudaGetSymbolAddress((void**)&VTh, g_VTh); cudaGetSymbolAddress((void**)&VTl, g_VTl);
    cudaGetSymbolAddress((void**)&P, g_P);
    cudaGetSymbolAddress((void**)&Ph, g_Ph);   cudaGetSymbolAddress((void**)&Pl, g_Pl);
    cudaGetSymbolAddress((void**)&ch, g_ch);   cudaGetSymbolAddress((void**)&cl, g_cl);
    cudaGetSymbolAddress((void**)&attn, g_attn);
    cudaGetSymbolAddress((void**)&xnh, g_xnh); cudaGetSymbolAddress((void**)&xnl, g_xnl);
    cudaGetSymbolAddress((void**)&fh, g_fh);   cudaGetSymbolAddress((void**)&fl, g_fl);

    const int SMEMB = NSTAGE * STAGE_B;   // 163840 (1 CTA/SM, deep prefetch)
    cudaFuncSetAttribute(mm_gemm<4,false,false>, cudaFuncAttributeMaxDynamicSharedMemorySize, SMEMB);
    cudaFuncSetAttribute(mm_gemm<5,false,false>, cudaFuncAttributeMaxDynamicSharedMemorySize, SMEMB);
    cudaFuncSetAttribute(mm_gemm<0,false,false>, cudaFuncAttributeMaxDynamicSharedMemorySize, SMEMB);
    cudaFuncSetAttribute(mm_gemm<1,true ,false>, cudaFuncAttributeMaxDynamicSharedMemorySize, SMEMB);
    cudaFuncSetAttribute(mm_gemm<4,false,true >, cudaFuncAttributeMaxDynamicSharedMemorySize, SMEMB);
    cudaFuncSetAttribute(mm_gemm<2,false,false>, cudaFuncAttributeMaxDynamicSharedMemorySize, SMEMB);
    cudaFuncSetAttribute(mm_gemm<3,false,false>, cudaFuncAttributeMaxDynamicSharedMemorySize, SMEMB);

    const long sSD  = (long)SS*DD;
    const long sBSD = (long)HH*SS*DD;

    // --- prep: fused flat splits + transposed weight splits ---
    split4_k<<<8192, 256>>>(x, xh, xl, OUT_E,
                            Wo, Woh, Wol, WO_E,
                            W1, W1h, W1l, W1_E,
                            W2, W2h, W2l, W1_E);
    {
        dim3 g(DD/32, DD/32, HH);
        split_t_k<<<g, 256>>>(Wq, WqTh, WqTl, DD, DD, (long)DD*DD, (long)DD*DD);
        split_t_k<<<g, 256>>>(Wk, WkTh, WkTl, DD, DD, (long)DD*DD, (long)DD*DD);
        split_t_k<<<g, 256>>>(Wv, WvTh, WvTl, DD, DD, (long)DD*DD, (long)DD*DD);
    }

    // --- Q, K projections (split out), V projection (TRANSPOSED split out) ---
    {
        dim3 g(DD/128, SS/128, BB*HH);
        mm_gemm<4,false,false><<<g, 256, SMEMB>>>(
            xh, xl, WqTh, WqTl, nullptr, Qh, Ql, nullptr,
            DD, DD, DD, DD, sSD, 0L, 0L, (long)DD*DD, sBSD, sSD, HH, 1.f);
        mm_gemm<4,false,false><<<g, 256, SMEMB>>>(
            xh, xl, WkTh, WkTl, nullptr, Kh, Kl, nullptr,
            DD, DD, DD, DD, sSD, 0L, 0L, (long)DD*DD, sBSD, sSD, HH, 1.f);
        // V^T stored directly: VT[b][h][d][s], ldc = SS (s-stride of d-rows)
        mm_gemm<5,false,false><<<g, 256, SMEMB>>>(
            xh, xl, WvTh, WvTl, nullptr, VTh, VTl, nullptr,
            DD, DD, DD, SS, sSD, 0L, 0L, (long)DD*DD, sBSD, sSD, HH, 1.f);
    }
    // --- scores = (Q K^T)/sqrt(D), causal tile skip, fp32 out ---
    {
        dim3 g(SS/128, SS/128, BB*HH);
        mm_gemm<1,true,false><<<g, 256, SMEMB>>>(
            Qh, Ql, Kh, Kl, P, nullptr, nullptr, nullptr,
            DD, DD, DD, SS, sBSD, sSD, sBSD, sSD,
            (long)HH*SS*SS, (long)SS*SS, HH, rsqrtf((float)DD));
    }
    // --- softmax -> hi/lo ---
    softmax_k<<<BB*HH*SS, 512>>>(P, Ph, Pl);
    // --- ctx = P V (K-limited), split output scattered to [B,S,H*D] ---
    {
        dim3 g(DD/128, SS/128, BB*HH);
        mm_gemm<4,false,true><<<g, 256, SMEMB>>>(
            Ph, Pl, VTh, VTl, nullptr, ch, cl, nullptr,
            SS, SS, SS, HH*DD,
            (long)HH*SS*SS, (long)SS*SS, (long)HH*DD*SS, (long)DD*SS,
            (long)SS*HH*DD, (long)DD, HH, 1.f);
    }
    // --- attn = ctx @ Wo^T (fp32) ---
    {
        dim3 g(DD/128, (BB*SS)/128, 1);
        mm_gemm<0,false,false><<<g, 256, SMEMB>>>(
            ch, cl, Woh, Wol, attn, nullptr, nullptr, nullptr,
            HH*DD, HH*DD, HH*DD, DD, 0L,0L,0L,0L,0L,0L, 1, 1.f);
    }
    // --- LN -> hi/lo ---
    ln_k<<<BB*SS, 256>>>(attn, xnh, xnl);
    // --- FFN1: GELU(xn @ W1^T) -> hi/lo ---
    {
        dim3 g(FF/128, (BB*SS)/128, 1);
        mm_gemm<2,false,false><<<g, 256, SMEMB>>>(
            xnh, xnl, W1h, W1l, nullptr, fh, fl, nullptr,
            DD, DD, DD, FF, 0L,0L,0L,0L,0L,0L, 1, 1.f);
    }
    // --- FFN2: out = attn + ffh @ W2^T ---
    {
        dim3 g(DD/128, (BB*SS)/128, 1);
        mm_gemm<3,false,false><<<g, 256, SMEMB>>>(
            fh, fl, W2h, W2l, out, nullptr, nullptr, attn,
            FF, FF, FF, DD, 0L,0L,0L,0L,0L,0L, 1, 1.f);
    }
}